// round 6
// baseline (speedup 1.0000x reference)
#include <cuda_runtime.h>
#include <math.h>

#define NPTS 32768
#define NB 16
#define WSTRIDE 4560   // per-batch hyper weights: 30*62 + 3*30*30

typedef unsigned long long u64;

// ---------------- scratch (device globals; no allocations allowed) ----------
__device__ float g_W[NB * WSTRIDE];          // normalized hyper weights
__device__ float g_enc[NPTS * 64];           // nerf encoding, padded to 64
__device__ float g_g[NB * NPTS * 30];        // output of hyper layers (63MB)

// ---------------- packed f32x2 helpers (Blackwell) ---------------------------
__device__ __forceinline__ u64 pk2(float lo, float hi) {
    u64 r; asm("mov.b64 %0,{%1,%2};" : "=l"(r) : "f"(lo), "f"(hi)); return r;
}
__device__ __forceinline__ float2 up2(u64 v) {
    float2 r; asm("mov.b64 {%0,%1},%2;" : "=f"(r.x), "=f"(r.y) : "l"(v)); return r;
}
__device__ __forceinline__ u64 fma2(u64 a, u64 b, u64 c) {
    u64 r; asm("fma.rn.f32x2 %0,%1,%2,%3;" : "=l"(r) : "l"(a), "l"(b), "l"(c));
    return r;
}
__device__ __forceinline__ u64 add2(u64 a, u64 b) {
    u64 r; asm("add.rn.f32x2 %0,%1,%2;" : "=l"(r) : "l"(a), "l"(b));
    return r;
}

// ---------------- misc helpers ----------------------------------------------
__device__ __forceinline__ float silu_f(float z) {
    float e = __expf(-z);
    return __fdividef(z, 1.0f + e);
}

// Pure-fp32 sin with 3-term Cody-Waite FMA reduction; accurate (~1e-7 abs)
// for |x| <= ~1e5 regardless of -use_fast_math. No FP64.
__device__ __forceinline__ float sin_cw(float x) {
    float kf = rintf(x * 0.63661977236758138f);
    float r = fmaf(kf, -1.57079637e+00f, x);
    r = fmaf(kf, 4.37113883e-08f, r);
    r = fmaf(kf, 1.71512489e-15f, r);
    int q = (int)kf;
    float s2 = r * r;
    float ps = fmaf(s2, 2.7525562e-6f, -1.9840874e-4f);
    ps = fmaf(s2, ps, 8.3333310e-3f);
    ps = fmaf(s2, ps, -1.6666667e-1f);
    float sinv = fmaf(r * s2, ps, r);
    float pc = fmaf(s2, 2.4433157e-5f, -1.3888378e-3f);
    pc = fmaf(s2, pc, 4.1666638e-2f);
    pc = fmaf(s2, pc, -0.5f);
    float cosv = fmaf(s2, pc, 1.0f);
    float res = (q & 1) ? cosv : sinv;
    if (q & 2) res = -res;
    return res;
}

// ---------------- K0: nerf encoding (all fp32) -------------------------------
__global__ __launch_bounds__(256) void enc_kernel(const float* __restrict__ x) {
    int p = blockIdx.x * 256 + threadIdx.x;
    float x0 = x[2 * p], x1 = x[2 * p + 1];
    float* o = g_enc + p * 64;
    const float HPI = 1.5707963267948966f;
    o[0] = x0; o[1] = x1;
#pragma unroll
    for (int s = 0; s < 15; ++s) {
        float sc = (float)(1 << s);
        float a0 = x0 * sc, a1 = x1 * sc;
        o[2 + 2 * s]  = sin_cw(a0);
        o[3 + 2 * s]  = sin_cw(a1);
        o[32 + 2 * s] = sin_cw(a0 + HPI);
        o[33 + 2 * s] = sin_cw(a1 + HPI);
    }
    o[62] = 0.0f; o[63] = 0.0f;
}

// ---------------- K1: fused hyper weight generation (all 4 layers) ----------
struct HP {
    const float* pw[4];
    const float* pb[4];
    const float* lnw[4];
    const float* lnb[4];
};

__global__ __launch_bounds__(256) void hyperw_kernel(const float* __restrict__ sdf, HP hp) {
    __shared__ float wbuf[30 * 62];
    int b  = blockIdx.x & 15;
    int li = blockIdx.x >> 4;
    int c    = (li == 0) ? 62 : 30;
    int woff = (li == 0) ? 0  : 1860 + (li - 1) * 900;
    const float* pw  = hp.pw[li];
    const float* pb  = hp.pb[li];
    const float* lnw = hp.lnw[li];
    const float* lnb = hp.lnb[li];

    int tid = threadIdx.x;
    int tot = 30 * c;
    for (int e = tid; e < tot; e += 256) {
        int v = e / c, cc = e - v * c;
        const float4* sl4 = (const float4*)(sdf + ((b * 120) + li * 30 + v) * 120);
        const float4* pw4 = (const float4*)(pw + (v * c + cc) * 120);
        float acc = 0.0f;
#pragma unroll
        for (int d = 0; d < 30; ++d) {
            float4 a = sl4[d], w = pw4[d];
            acc = fmaf(a.x, w.x, acc); acc = fmaf(a.y, w.y, acc);
            acc = fmaf(a.z, w.z, acc); acc = fmaf(a.w, w.w, acc);
        }
        wbuf[e] = acc + pb[e];
    }
    __syncthreads();
    if (tid < 30) {
        int v = tid;
        const float* row = wbuf + v * c;
        float mu = 0.0f;
        for (int cc = 0; cc < c; ++cc) mu += row[cc];
        mu /= (float)c;
        float var = 0.0f;
        for (int cc = 0; cc < c; ++cc) { float d = row[cc] - mu; var = fmaf(d, d, var); }
        var /= (float)c;
        float inv = rsqrtf(var + 1e-5f);
        float* dst = g_W + b * WSTRIDE + woff + v * c;
        for (int cc = 0; cc < c; ++cc)
            dst[cc] = (row[cc] - mu) * inv * lnw[cc] + lnb[cc];
    }
}

// ---------------- K2: apply 4 hyper layers (f32x2 packed) --------------------
__global__ __launch_bounds__(256) void hyper_apply_kernel(
    const float* __restrict__ b0, const float* __restrict__ b1,
    const float* __restrict__ b2, const float* __restrict__ b3) {
    __shared__ float sW[WSTRIDE];
    __shared__ float sb[120];
    int b = blockIdx.y;
    int tid = threadIdx.x;
    const float* Wb = g_W + b * WSTRIDE;
    for (int i = tid; i < WSTRIDE; i += 256) sW[i] = Wb[i];
    if (tid < 30) sb[tid] = b0[tid];
    else if (tid < 60) sb[tid] = b1[tid - 30];
    else if (tid < 90) sb[tid] = b2[tid - 60];
    else if (tid < 120) sb[tid] = b3[tid - 90];
    __syncthreads();

    int p = blockIdx.x * 256 + tid;
    u64 hpr[31];
    const u64* e8 = (const u64*)(g_enc + p * 64);
#pragma unroll
    for (int i = 0; i < 31; ++i) hpr[i] = e8[i];

    float a[30];
#pragma unroll
    for (int oo = 0; oo < 30; ++oo) {
        const u64* w8 = (const u64*)(sW + oo * 62);
        u64 acc = 0ull;
#pragma unroll
        for (int i = 0; i < 31; ++i) acc = fma2(hpr[i], w8[i], acc);
        float2 f = up2(acc);
        a[oo] = silu_f(f.x + f.y + sb[oo]);
    }
#pragma unroll
    for (int l = 1; l <= 3; ++l) {
        int off = 1860 + (l - 1) * 900;
        u64 ap[15];
#pragma unroll
        for (int i = 0; i < 15; ++i) ap[i] = pk2(a[2 * i], a[2 * i + 1]);
        float t[30];
#pragma unroll
        for (int oo = 0; oo < 30; ++oo) {
            const u64* w8 = (const u64*)(sW + off + oo * 30);
            u64 acc = 0ull;
#pragma unroll
            for (int i = 0; i < 15; ++i) acc = fma2(ap[i], w8[i], acc);
            float2 f = up2(acc);
            t[oo] = silu_f(f.x + f.y + sb[l * 30 + oo]);
        }
#pragma unroll
        for (int oo = 0; oo < 30; ++oo) a[oo] = t[oo];
    }
    u64* gout = (u64*)(g_g + ((size_t)b * NPTS + p) * 30);
#pragma unroll
    for (int i = 0; i < 15; ++i) gout[i] = pk2(a[2 * i], a[2 * i + 1]);
}

// ---------------- K3: persistent fused MLP -----------------------------------
// Per item (64-point tile x batch):
//   phase1: thread = (kp, ph): 2 h1-rows x 32 points-half, w0 rows in regs
//   GEMM2:  thread = (ks, jg, pg): 16 j x 8 pts (4 u64), k-split 4 + smem reduce
// smem (floats):
//   sW1 [256][132] at 0        (33792)
//   sS  [256][68]  at 33792    (17408)   also k-split reduction scratch
//   sGp [15][132]  at 51200    ( 1980)   g pairs, half-shift swizzle; also sRedE
//   sB1 at 53180, sW2 at 53308
#define K3_SMEM_FLOATS 53440
#define K3_SMEM_BYTES (K3_SMEM_FLOATS * 4)
#define TILE_P 64
#define MLP_BLOCKS 148
#define N_ITEMS ((NPTS / TILE_P) * NB)   // 8192

__global__ __launch_bounds__(256, 1) void mlp_kernel(
    const float* __restrict__ w0, const float* __restrict__ b0,
    const float* __restrict__ w1, const float* __restrict__ b1,
    const float* __restrict__ w2, const float* __restrict__ b2v,
    float* __restrict__ out) {
    extern __shared__ float sm[];
    float* sW1  = sm;                 // [256][132] k-major
    float* sS   = sm + 33792;         // [256][68]
    float* sGpf = sm + 51200;         // [15][132]
    u64*   sGp  = (u64*)sGpf;
    float* sB1  = sm + 53180;
    float* sW2  = sm + 53308;

    int tid = threadIdx.x;
#pragma unroll 4
    for (int i = 0; i < 128; ++i)
        sW1[tid * 132 + i] = w1[i * 256 + tid];
    if (tid < 128) { sB1[tid] = b1[tid]; sW2[tid] = w2[tid]; }
    float bias2 = __ldg(b2v);

    // phase1 coords
    int kp = tid >> 1, ph = tid & 1;
    float b00 = b0[2 * kp], b01 = b0[2 * kp + 1];
    const u64* w0g = (const u64*)(w0 + kp * 60);   // rows 2kp, 2kp+1 contiguous

    // GEMM2 coords
    int ks = tid >> 6, rem = tid & 63, jg = rem >> 3, pg = rem & 7;
    int j0 = jg * 16;

#pragma unroll 1
    for (int item = blockIdx.x; item < N_ITEMS; item += MLP_BLOCKS) {
        int p0base = (item >> 4) * TILE_P;
        int b = item & 15;

        // ---- load g tile into sGp with half-shift swizzle ----
        for (int idx = tid; idx < 960; idx += 256) {
            int p = idx / 15, i = idx - p * 15;
            sGp[i * 66 + p + 2 * (p >> 5)] =
                *(const u64*)(g_g + ((size_t)b * NPTS + p0base + p) * 30 + 2 * i);
        }
        __syncthreads();

        // ---- phase 1: 2 rows x 32 points-half per thread ----
        {
            // w0 rows via asm volatile so regs don't persist across item loop
            u64 w0r0[15], w0r1[15];
#pragma unroll
            for (int i = 0; i < 15; ++i) {
                asm volatile("ld.global.nc.b64 %0,[%1];"
                             : "=l"(w0r0[i]) : "l"(w0g + i));
                asm volatile("ld.global.nc.b64 %0,[%1];"
                             : "=l"(w0r1[i]) : "l"(w0g + 15 + i));
            }
            const float* gb = sGpf + ph * 68;
#pragma unroll 1
            for (int pb = 0; pb < 8; ++pb) {
                u64 a00 = 0, a01 = 0, a02 = 0, a03 = 0;
                u64 a10 = 0, a11 = 0, a12 = 0, a13 = 0;
#pragma unroll
                for (int i = 0; i < 15; ++i) {
                    ulonglong2 gA = *(const ulonglong2*)(gb + i * 132 + pb * 8);
                    ulonglong2 gB = *(const ulonglong2*)(gb + i * 132 + pb * 8 + 4);
                    a00 = fma2(w0r0[i], gA.x, a00); a01 = fma2(w0r0[i], gA.y, a01);
                    a02 = fma2(w0r0[i], gB.x, a02); a03 = fma2(w0r0[i], gB.y, a03);
                    a10 = fma2(w0r1[i], gA.x, a10); a11 = fma2(w0r1[i], gA.y, a11);
                    a12 = fma2(w0r1[i], gB.x, a12); a13 = fma2(w0r1[i], gB.y, a13);
                }
                float4 s0v, s1v; float2 f;
                f = up2(a00); s0v.x = silu_f(f.x + f.y + b00);
                f = up2(a01); s0v.y = silu_f(f.x + f.y + b00);
                f = up2(a02); s0v.z = silu_f(f.x + f.y + b00);
                f = up2(a03); s0v.w = silu_f(f.x + f.y + b00);
                f = up2(a10); s1v.x = silu_f(f.x + f.y + b01);
                f = up2(a11); s1v.y = silu_f(f.x + f.y + b01);
                f = up2(a12); s1v.z = silu_f(f.x + f.y + b01);
                f = up2(a13); s1v.w = silu_f(f.x + f.y + b01);
                *(float4*)(sS + (2 * kp) * 68 + ph * 32 + pb * 4) = s0v;
                *(float4*)(sS + (2 * kp + 1) * 68 + ph * 32 + pb * 4) = s1v;
            }
        }
        __syncthreads();

        // ---- GEMM2: 16j x 4 u64-points, k in [ks*64, ks*64+64) ----
        u64 c[16][4];
#pragma unroll
        for (int jj = 0; jj < 16; ++jj) {
            u64 init = 0ull;
            if (ks == 0) { float bv = sB1[j0 + jj]; init = pk2(bv, bv); }
            c[jj][0] = init; c[jj][1] = init; c[jj][2] = init; c[jj][3] = init;
        }
        {
            const float* wbase = sW1 + j0;
            const float* sbase = sS + pg * 2;
            int kend = ks * 64 + 64;
#pragma unroll 2
            for (int k = ks * 64; k < kend; ++k) {
                const float4* wr = (const float4*)(wbase + k * 132);
                float4 wv0 = wr[0], wv1 = wr[1], wv2 = wr[2], wv3 = wr[3];
                const float* sr = sbase + k * 68;
                u64 s0 = *(const u64*)(sr);
                u64 s1 = *(const u64*)(sr + 16);
                u64 s2 = *(const u64*)(sr + 32);
                u64 s3 = *(const u64*)(sr + 48);
                float wf[16] = {wv0.x, wv0.y, wv0.z, wv0.w,
                                wv1.x, wv1.y, wv1.z, wv1.w,
                                wv2.x, wv2.y, wv2.z, wv2.w,
                                wv3.x, wv3.y, wv3.z, wv3.w};
#pragma unroll
                for (int jj = 0; jj < 16; ++jj) {
                    u64 wp = pk2(wf[jj], wf[jj]);
                    c[jj][0] = fma2(wp, s0, c[jj][0]);
                    c[jj][1] = fma2(wp, s1, c[jj][1]);
                    c[jj][2] = fma2(wp, s2, c[jj][2]);
                    c[jj][3] = fma2(wp, s3, c[jj][3]);
                }
            }
        }

        // ---- k-split reduction through sS scratch (2 rounds) ----
        u64* red = (u64*)sS;
        __syncthreads();
        if (tid >= 128) {
            ulonglong2* dst = (ulonglong2*)(red + (tid - 128) * 68);
#pragma unroll
            for (int jj = 0; jj < 16; ++jj) {
                dst[2 * jj]     = make_ulonglong2(c[jj][0], c[jj][1]);
                dst[2 * jj + 1] = make_ulonglong2(c[jj][2], c[jj][3]);
            }
        }
        __syncthreads();
        if (tid < 128) {
            const u64* src = red + tid * 68;
#pragma unroll
            for (int jj = 0; jj < 16; ++jj) {
                c[jj][0] = add2(c[jj][0], src[4 * jj]);
                c[jj][1] = add2(c[jj][1], src[4 * jj + 1]);
                c[jj][2] = add2(c[jj][2], src[4 * jj + 2]);
                c[jj][3] = add2(c[jj][3], src[4 * jj + 3]);
            }
        }
        __syncthreads();
        if (tid >= 64 && tid < 128) {
            ulonglong2* dst = (ulonglong2*)(red + (tid - 64) * 68);
#pragma unroll
            for (int jj = 0; jj < 16; ++jj) {
                dst[2 * jj]     = make_ulonglong2(c[jj][0], c[jj][1]);
                dst[2 * jj + 1] = make_ulonglong2(c[jj][2], c[jj][3]);
            }
        }
        __syncthreads();
        if (tid < 64) {
            const u64* src = red + tid * 68;
            float r[8];
#pragma unroll
            for (int e = 0; e < 8; ++e) r[e] = 0.0f;
#pragma unroll
            for (int jj = 0; jj < 16; ++jj) {
                float wj = sW2[j0 + jj];
                u64 t0 = add2(c[jj][0], src[4 * jj]);
                u64 t1 = add2(c[jj][1], src[4 * jj + 1]);
                u64 t2 = add2(c[jj][2], src[4 * jj + 2]);
                u64 t3 = add2(c[jj][3], src[4 * jj + 3]);
                float2 f;
                f = up2(t0); r[0] = fmaf(wj, silu_f(f.x), r[0]);
                             r[1] = fmaf(wj, silu_f(f.y), r[1]);
                f = up2(t1); r[2] = fmaf(wj, silu_f(f.x), r[2]);
                             r[3] = fmaf(wj, silu_f(f.y), r[3]);
                f = up2(t2); r[4] = fmaf(wj, silu_f(f.x), r[4]);
                             r[5] = fmaf(wj, silu_f(f.y), r[5]);
                f = up2(t3); r[6] = fmaf(wj, silu_f(f.x), r[6]);
                             r[7] = fmaf(wj, silu_f(f.y), r[7]);
            }
            // partials to sGp region (dead until next item's g-load)
            ((float4*)(sGpf + tid * 8))[0] = make_float4(r[0], r[1], r[2], r[3]);
            ((float4*)(sGpf + tid * 8))[1] = make_float4(r[4], r[5], r[6], r[7]);
        }
        __syncthreads();
        if (tid < 64) {
            int p = tid;
            int u = p >> 4, par = p & 1, pg2 = (p >> 1) & 7;
            int e = 2 * u + par;
            float s = bias2;
#pragma unroll
            for (int jg2 = 0; jg2 < 8; ++jg2)
                s += sGpf[(jg2 * 8 + pg2) * 8 + e];
            out[(size_t)b * NPTS + p0base + p] = s;
        }
        __syncthreads();
    }
}

// ---------------- launch -----------------------------------------------------
extern "C" void kernel_launch(void* const* d_in, const int* in_sizes, int n_in,
                              void* d_out, int out_size) {
    const float* x   = (const float*)d_in[0];
    const float* sdf = (const float*)d_in[1];
    HP hp;
    hp.pw[0]  = (const float*)d_in[2];  hp.pw[1]  = (const float*)d_in[7];
    hp.pw[2]  = (const float*)d_in[12]; hp.pw[3]  = (const float*)d_in[17];
    hp.pb[0]  = (const float*)d_in[3];  hp.pb[1]  = (const float*)d_in[8];
    hp.pb[2]  = (const float*)d_in[13]; hp.pb[3]  = (const float*)d_in[18];
    hp.lnw[0] = (const float*)d_in[4];  hp.lnw[1] = (const float*)d_in[9];
    hp.lnw[2] = (const float*)d_in[14]; hp.lnw[3] = (const float*)d_in[19];
    hp.lnb[0] = (const float*)d_in[5];  hp.lnb[1] = (const float*)d_in[10];
    hp.lnb[2] = (const float*)d_in[15]; hp.lnb[3] = (const float*)d_in[20];
    const float* bias[4] = {(const float*)d_in[6],  (const float*)d_in[11],
                            (const float*)d_in[16], (const float*)d_in[21]};
    const float* mw0 = (const float*)d_in[22];
    const float* mb0 = (const float*)d_in[23];
    const float* mw1 = (const float*)d_in[24];
    const float* mb1 = (const float*)d_in[25];
    const float* mw2 = (const float*)d_in[26];
    const float* mb2 = (const float*)d_in[27];
    float* out = (float*)d_out;

    cudaFuncSetAttribute(mlp_kernel, cudaFuncAttributeMaxDynamicSharedMemorySize,
                         K3_SMEM_BYTES);

    enc_kernel<<<NPTS / 256, 256>>>(x);
    hyperw_kernel<<<NB * 4, 256>>>(sdf, hp);

    dim3 g2(NPTS / 256, NB);
    hyper_apply_kernel<<<g2, 256>>>(bias[0], bias[1], bias[2], bias[3]);

    mlp_kernel<<<MLP_BLOCKS, 256, K3_SMEM_BYTES>>>(mw0, mb0, mw1, mb1, mw2, mb2, out);
}